// round 1
// baseline (speedup 1.0000x reference)
#include <cuda_runtime.h>
#include <math.h>

// Problem constants
#define B_   4
#define C_   256
#define CO_  256
#define H_   256
#define W_   256
#define NTOT 85          // 64 (g=8) + 16 (g=4) + 4 (g=2) + 1 (g=1)
#define L3B  0
#define L2B  64
#define L1B  80
#define L0B  84
#define ROWS 32          // 1 + 4 + 8 + 19 kept rows per batch

// Output offsets (floats): (out, sparse_seq, all_coords, sparsity)
#define OFS_DENSE    0ull
#define OFS_SPARSE   67108864ull                    // 4*256*256*256
#define OFS_COORDS   (67108864ull + 32768ull)       // + 4*32*256
#define OFS_SPARSITY (67108864ull + 32768ull + 512ull)

// Scratch (device globals — no allocations allowed)
__device__ float g_pyr[B_][C_][NTOT];   // all pyramid levels, per channel
__device__ float g_l2sq[B_][NTOT];      // sum over C of v^2 per cell
__device__ int   g_sel[B_][ROWS];       // kept cell index into [0,85) per row
__device__ int   g_map8[B_][64];        // finest-kept row per 8x8 fine cell

// ---------------------------------------------------------------------------
// K1: grid max pool x -> pyr3 (g=8). One block per (b, c, cell8).
// Each block reduces a 32x32 tile with float4 loads (fully coalesced).
// ---------------------------------------------------------------------------
__global__ void k_pool(const float* __restrict__ x) {
    int cell = blockIdx.x & 63;
    int bc   = blockIdx.x >> 6;
    int c    = bc & 255;
    int b    = bc >> 8;
    int gy   = cell >> 3, gx = cell & 7;

    const float* base = x + ((size_t)(b * 256 + c) * 256 + (size_t)gy * 32) * 256 + gx * 32;
    int t   = threadIdx.x;           // 256 threads
    int row = t >> 3, q = t & 7;     // 32 rows x 8 float4 each
    float4 v = *reinterpret_cast<const float4*>(base + (size_t)row * 256 + q * 4);
    float m = fmaxf(fmaxf(v.x, v.y), fmaxf(v.z, v.w));

    #pragma unroll
    for (int o = 16; o > 0; o >>= 1)
        m = fmaxf(m, __shfl_xor_sync(0xffffffffu, m, o));
    __shared__ float sm[8];
    if ((t & 31) == 0) sm[t >> 5] = m;
    __syncthreads();
    if (t == 0) {
        float r = sm[0];
        #pragma unroll
        for (int i = 1; i < 8; i++) r = fmaxf(r, sm[i]);
        g_pyr[b][c][cell] = r;
    }
}

// ---------------------------------------------------------------------------
// K2: build pyr2/pyr1/pyr0 from pyr3 via 2x2 maxes. One block per (b, c).
// ---------------------------------------------------------------------------
__global__ void k_pyr_up() {
    int bc = blockIdx.x;
    int c  = bc & 255;
    int b  = bc >> 8;
    __shared__ float s[84];
    int t = threadIdx.x;  // 64 threads
    s[t] = g_pyr[b][c][t];
    __syncthreads();
    if (t < 16) {
        int gy = t >> 2, gx = t & 3;
        float v = fmaxf(fmaxf(s[(2 * gy) * 8 + 2 * gx],     s[(2 * gy) * 8 + 2 * gx + 1]),
                        fmaxf(s[(2 * gy + 1) * 8 + 2 * gx], s[(2 * gy + 1) * 8 + 2 * gx + 1]));
        s[64 + t] = v;
        g_pyr[b][c][L2B + t] = v;
    }
    __syncthreads();
    if (t < 4) {
        int gy = t >> 1, gx = t & 1;
        float v = fmaxf(fmaxf(s[64 + (2 * gy) * 4 + 2 * gx],     s[64 + (2 * gy) * 4 + 2 * gx + 1]),
                        fmaxf(s[64 + (2 * gy + 1) * 4 + 2 * gx], s[64 + (2 * gy + 1) * 4 + 2 * gx + 1]));
        s[80 + t] = v;
        g_pyr[b][c][L1B + t] = v;
    }
    __syncthreads();
    if (t == 0) {
        g_pyr[b][c][L0B] = fmaxf(fmaxf(s[80], s[81]), fmaxf(s[82], s[83]));
    }
}

// ---------------------------------------------------------------------------
// K3: squared L2 norm over channels per cell. One block per (b, cell).
// ---------------------------------------------------------------------------
__global__ void k_l2() {
    int cell = blockIdx.x % NTOT;
    int b    = blockIdx.x / NTOT;
    int t    = threadIdx.x;  // 256 threads (= channels)
    float v = g_pyr[b][t][cell];
    float s = v * v;
    #pragma unroll
    for (int o = 16; o > 0; o >>= 1)
        s += __shfl_xor_sync(0xffffffffu, s, o);
    __shared__ float sm[8];
    if ((t & 31) == 0) sm[t >> 5] = s;
    __syncthreads();
    if (t == 0) {
        float r = 0.f;
        #pragma unroll
        for (int i = 0; i < 8; i++) r += sm[i];
        g_l2sq[b][cell] = r;
    }
}

// ---------------------------------------------------------------------------
// K4: importance + top-k per level (matches lax.top_k ordering: descending,
// ties -> lower index), write coords, build fine-cell row map, sparsity.
// Tiny (N<=64, k<=19): one thread per batch.
// ---------------------------------------------------------------------------
__device__ __forceinline__ void select_topk(const float* imp, int n, int k, int* order) {
    bool used[64];
    for (int i = 0; i < n; i++) used[i] = false;
    for (int r = 0; r < k; r++) {
        int best = -1;
        float bv = 0.f;
        for (int i = 0; i < n; i++) {
            if (used[i]) continue;
            if (best < 0 || imp[i] > bv) { bv = imp[i]; best = i; }
        }
        used[best] = true;
        order[r] = best;
    }
}

__global__ void k_topk(float* __restrict__ dout) {
    int b = blockIdx.x;
    if (threadIdx.x != 0) return;

    float l2[NTOT];
    for (int i = 0; i < NTOT; i++) l2[i] = sqrtf(g_l2sq[b][i]);

    float imp[64];
    int order[19];
    int rank3[64], rank2[16], rank1[4];
    for (int i = 0; i < 64; i++) rank3[i] = -1;
    for (int i = 0; i < 16; i++) rank2[i] = -1;

    // --- level 0: g=1, k=1, row 0 ---
    {
        // imp = |l2_level0 - l2(level1 cell (0,0))| but k==N==1 regardless
        g_sel[b][0] = L0B;
        float* cp = dout + OFS_COORDS + ((size_t)b * ROWS + 0) * 4;
        cp[0] = 0.5f; cp[1] = 0.5f; cp[2] = 1.0f; cp[3] = 1.0f;
    }
    // --- level 1: g=2, k=4, rows 1..4 ---
    {
        for (int n = 0; n < 4; n++) {
            int gy = n >> 1, gx = n & 1;
            imp[n] = fabsf(l2[L1B + n] - l2[L2B + (2 * gy) * 4 + 2 * gx]);
        }
        select_topk(imp, 4, 4, order);
        for (int r = 0; r < 4; r++) {
            int cell = order[r];
            rank1[cell] = r;
            g_sel[b][1 + r] = L1B + cell;
            int gy = cell >> 1, gx = cell & 1;
            float* cp = dout + OFS_COORDS + ((size_t)b * ROWS + 1 + r) * 4;
            cp[0] = (gx + 0.5f) * 0.5f; cp[1] = (gy + 0.5f) * 0.5f;
            cp[2] = 0.5f; cp[3] = 0.5f;
        }
    }
    // --- level 2: g=4, k=8, rows 5..12 ---
    {
        for (int n = 0; n < 16; n++) {
            int gy = n >> 2, gx = n & 3;
            imp[n] = fabsf(l2[L2B + n] - l2[L3B + (2 * gy) * 8 + 2 * gx]);
        }
        select_topk(imp, 16, 8, order);
        for (int r = 0; r < 8; r++) {
            int cell = order[r];
            rank2[cell] = r;
            g_sel[b][5 + r] = L2B + cell;
            int gy = cell >> 2, gx = cell & 3;
            float* cp = dout + OFS_COORDS + ((size_t)b * ROWS + 5 + r) * 4;
            cp[0] = (gx + 0.5f) * 0.25f; cp[1] = (gy + 0.5f) * 0.25f;
            cp[2] = 0.25f; cp[3] = 0.25f;
        }
    }
    // --- level 3: g=8, k=19, rows 13..31 ---
    {
        for (int n = 0; n < 64; n++) imp[n] = l2[L3B + n];
        select_topk(imp, 64, 19, order);
        for (int r = 0; r < 19; r++) {
            int cell = order[r];
            rank3[cell] = r;
            g_sel[b][13 + r] = L3B + cell;
            int gy = cell >> 3, gx = cell & 7;
            float* cp = dout + OFS_COORDS + ((size_t)b * ROWS + 13 + r) * 4;
            cp[0] = (gx + 0.5f) * 0.125f; cp[1] = (gy + 0.5f) * 0.125f;
            cp[2] = 0.125f; cp[3] = 0.125f;
        }
    }
    // --- fine-cell -> row map (finest kept level wins; level1 covers all) ---
    for (int cell = 0; cell < 64; cell++) {
        int gy = cell >> 3, gx = cell & 7;
        int row;
        if (rank3[cell] >= 0) {
            row = 13 + rank3[cell];
        } else {
            int c2 = (gy >> 1) * 4 + (gx >> 1);
            if (rank2[c2] >= 0) {
                row = 5 + rank2[c2];
            } else {
                int c1 = (gy >> 2) * 2 + (gx >> 2);
                row = 1 + rank1[c1];
            }
        }
        g_map8[b][cell] = row;
    }
    if (b == 0) dout[OFS_SPARSITY] = 32.0f / 65536.0f;
}

// ---------------------------------------------------------------------------
// K5: LayerNorm + Linear(256->256) on the 128 kept rows. One block per row.
// ---------------------------------------------------------------------------
__global__ void k_proj(const float* __restrict__ ln_g, const float* __restrict__ ln_b,
                       const float* __restrict__ w, const float* __restrict__ bias,
                       float* __restrict__ dout) {
    int row = blockIdx.x & 31;
    int b   = blockIdx.x >> 5;
    int t   = threadIdx.x;   // 256 threads (= channels / outputs)
    int gcell = g_sel[b][row];
    float v = g_pyr[b][t][gcell];

    __shared__ float sred[8];
    // mean
    float s = v;
    #pragma unroll
    for (int o = 16; o > 0; o >>= 1) s += __shfl_xor_sync(0xffffffffu, s, o);
    if ((t & 31) == 0) sred[t >> 5] = s;
    __syncthreads();
    float mean = 0.f;
    #pragma unroll
    for (int i = 0; i < 8; i++) mean += sred[i];
    mean *= (1.0f / 256.0f);
    __syncthreads();
    // variance
    float d = v - mean;
    float s2 = d * d;
    #pragma unroll
    for (int o = 16; o > 0; o >>= 1) s2 += __shfl_xor_sync(0xffffffffu, s2, o);
    if ((t & 31) == 0) sred[t >> 5] = s2;
    __syncthreads();
    float var = 0.f;
    #pragma unroll
    for (int i = 0; i < 8; i++) var += sred[i];
    var *= (1.0f / 256.0f);

    float kfn = d * (1.0f / sqrtf(var + 1e-5f)) * ln_g[t] + ln_b[t];
    __shared__ float skf[256];
    skf[t] = kfn;
    __syncthreads();

    float acc = bias[t];
    #pragma unroll 8
    for (int c = 0; c < 256; c++)
        acc = fmaf(skf[c], w[c * 256 + t], acc);

    dout[OFS_SPARSE + ((size_t)(b * 32 + row)) * 256 + t] = acc;
}

// ---------------------------------------------------------------------------
// K6: dense fill. One block per (b, d, y8-strip of 32 rows). Pure float4 fill.
// ---------------------------------------------------------------------------
__global__ void k_fill(float* __restrict__ dout) {
    int y8 = blockIdx.x & 7;
    int d  = (blockIdx.x >> 3) & 255;
    int b  = blockIdx.x >> 11;
    int t  = threadIdx.x;   // 256 threads

    __shared__ float sv[8];
    if (t < 8) {
        int row = g_map8[b][y8 * 8 + t];
        sv[t] = dout[OFS_SPARSE + ((size_t)(b * 32 + row)) * 256 + d];
    }
    __syncthreads();

    float4* base = reinterpret_cast<float4*>(
        dout + ((size_t)((b * 256 + d) * 256 + y8 * 32)) * 256);
    #pragma unroll
    for (int i = 0; i < 8; i++) {
        int f  = t + i * 256;       // float4 index within the 32x256 slab
        int x4 = f & 63;
        float v = sv[x4 >> 3];
        base[f] = make_float4(v, v, v, v);
    }
}

// ---------------------------------------------------------------------------
extern "C" void kernel_launch(void* const* d_in, const int* in_sizes, int n_in,
                              void* d_out, int out_size) {
    const float* x    = (const float*)d_in[0];
    const float* ln_g = (const float*)d_in[1];
    const float* ln_b = (const float*)d_in[2];
    const float* w    = (const float*)d_in[3];
    const float* bias = (const float*)d_in[4];
    float* out = (float*)d_out;
    (void)in_sizes; (void)n_in; (void)out_size;

    k_pool<<<B_ * C_ * 64, 256>>>(x);
    k_pyr_up<<<B_ * C_, 64>>>();
    k_l2<<<B_ * NTOT, 256>>>();
    k_topk<<<B_, 1>>>(out);
    k_proj<<<B_ * ROWS, 256>>>(ln_g, ln_b, w, bias, out);
    k_fill<<<B_ * CO_ * 8, 256>>>(out);
}

// round 2
// speedup vs baseline: 1.0983x; 1.0983x over previous
#include <cuda_runtime.h>
#include <math.h>

#define B_   4
#define C_   256
#define CO_  256
#define H_   256
#define W_   256
#define NTOT 85          // 64 (g=8) + 16 (g=4) + 4 (g=2) + 1 (g=1)
#define L3B  0
#define L2B  64
#define L1B  80
#define L0B  84
#define ROWS 32          // 1 + 4 + 8 + 19 kept rows per batch

// Output offsets (floats): (out, sparse_seq, all_coords, sparsity)
#define OFS_DENSE    0ull
#define OFS_SPARSE   67108864ull                    // 4*256*256*256
#define OFS_COORDS   (67108864ull + 32768ull)       // + 4*32*256
#define OFS_SPARSITY (67108864ull + 32768ull + 512ull)

#define NEG_INF __int_as_float(0xff800000)

// Scratch (device globals — allocations forbidden). Cell-major for coalescing.
__device__ float g_pyr[B_][NTOT][C_];   // pyramid, cell-major
__device__ int   g_sel[B_][ROWS];       // kept cell index [0,85) per row
__device__ int   g_map8[B_][64];        // finest-kept row per 8x8 fine cell

// ---------------------------------------------------------------------------
// K1: grid max pool x -> pyr3 (g=8). One block per (b, c, gy-strip).
// 8 float4 loads per thread (MLP=8), then 8 warp reductions.
// ---------------------------------------------------------------------------
__global__ void k_pool(const float* __restrict__ x) {
    int gy = blockIdx.x & 7;
    int bc = blockIdx.x >> 3;
    int c  = bc & 255;
    int b  = bc >> 8;

    const float4* base4 = reinterpret_cast<const float4*>(
        x + ((size_t)(b * 256 + c) * 256 + (size_t)gy * 32) * 256);
    int t = threadIdx.x;          // 256 threads
    int r = t >> 3, j = t & 7;    // row 0..31, float4-within-cell 0..7
    int w = t >> 5;

    float4 v[8];
    #pragma unroll
    for (int gx = 0; gx < 8; gx++)
        v[gx] = base4[r * 64 + gx * 8 + j];

    __shared__ float sm[8][8];    // [gx][warp]
    #pragma unroll
    for (int gx = 0; gx < 8; gx++) {
        float m = fmaxf(fmaxf(v[gx].x, v[gx].y), fmaxf(v[gx].z, v[gx].w));
        #pragma unroll
        for (int o = 16; o > 0; o >>= 1)
            m = fmaxf(m, __shfl_xor_sync(0xffffffffu, m, o));
        if ((t & 31) == 0) sm[gx][w] = m;
    }
    __syncthreads();
    if (t < 64) {
        int gx = t >> 3, p = t & 7;
        float m = sm[gx][p];
        #pragma unroll
        for (int o = 4; o > 0; o >>= 1)
            m = fmaxf(m, __shfl_xor_sync(0xffffffffu, m, o));
        if (p == 0) g_pyr[b][gy * 8 + gx][c] = m;
    }
}

// ---------------------------------------------------------------------------
// K2: per-batch prep: pyramid upper levels + L2 norms + top-k + coords + map.
// One block of 256 threads per batch.
// ---------------------------------------------------------------------------
__device__ __forceinline__ void warp_argmax(float& v, int& i) {
    #pragma unroll
    for (int o = 16; o > 0; o >>= 1) {
        float ov = __shfl_xor_sync(0xffffffffu, v, o);
        int   oi = __shfl_xor_sync(0xffffffffu, i, o);
        if (ov > v || (ov == v && oi < i)) { v = ov; i = oi; }
    }
}

__global__ void k_prep(float* __restrict__ dout) {
    int b = blockIdx.x;
    int t = threadIdx.x;          // 256 threads (= channel in phase A)
    int lane = t & 31, w = t >> 5;

    // --- phase A: upper pyramid levels (per-channel, fully coalesced) ---
    float v2a[16];
    #pragma unroll
    for (int u = 0; u < 16; u++) {
        int gy = u >> 2, gx = u & 3;
        int c0 = (gy * 2) * 8 + gx * 2;
        float v = fmaxf(fmaxf(g_pyr[b][c0][t],     g_pyr[b][c0 + 1][t]),
                        fmaxf(g_pyr[b][c0 + 8][t], g_pyr[b][c0 + 9][t]));
        v2a[u] = v;
        g_pyr[b][L2B + u][t] = v;
    }
    float v1a[4];
    #pragma unroll
    for (int u = 0; u < 4; u++) {
        int gy = u >> 1, gx = u & 1;
        int c0 = (gy * 2) * 4 + gx * 2;
        float v = fmaxf(fmaxf(v2a[c0], v2a[c0 + 1]), fmaxf(v2a[c0 + 4], v2a[c0 + 5]));
        v1a[u] = v;
        g_pyr[b][L1B + u][t] = v;
    }
    g_pyr[b][L0B][t] = fmaxf(fmaxf(v1a[0], v1a[1]), fmaxf(v1a[2], v1a[3]));
    __syncthreads();

    // --- phase B: L2 norms per cell (8 warps stripe the 85 cells) ---
    __shared__ float sl2[NTOT];
    for (int u = w; u < NTOT; u += 8) {
        float acc = 0.f;
        #pragma unroll
        for (int i = 0; i < 8; i++) {
            float v = g_pyr[b][u][lane + 32 * i];
            acc = fmaf(v, v, acc);
        }
        #pragma unroll
        for (int o = 16; o > 0; o >>= 1)
            acc += __shfl_xor_sync(0xffffffffu, acc, o);
        if (lane == 0) sl2[u] = sqrtf(acc);
    }
    __syncthreads();

    // --- phase C: top-k per level (warp 0 only) ---
    __shared__ int srank3[64], srank2[16], srank1[4];
    if (w == 0) {
        srank3[lane] = -1; srank3[lane + 32] = -1;
        if (lane < 16) srank2[lane] = -1;
        if (lane < 4)  srank1[lane] = -1;

        // level 0: g=1, k=1, row 0
        if (lane == 0) {
            g_sel[b][0] = L0B;
            float* cp = dout + OFS_COORDS + ((size_t)b * ROWS) * 4;
            cp[0] = 0.5f; cp[1] = 0.5f; cp[2] = 1.0f; cp[3] = 1.0f;
        }
        // level 1: g=2, k=4 (serial on lane 0, N=4)
        if (lane == 0) {
            float imp[4];
            #pragma unroll
            for (int n = 0; n < 4; n++) {
                int gy = n >> 1, gx = n & 1;
                imp[n] = fabsf(sl2[L1B + n] - sl2[L2B + (2 * gy) * 4 + 2 * gx]);
            }
            bool used[4] = {false, false, false, false};
            for (int r = 0; r < 4; r++) {
                int best = -1; float bv = 0.f;
                #pragma unroll
                for (int i = 0; i < 4; i++) {
                    if (used[i]) continue;
                    if (best < 0 || imp[i] > bv) { bv = imp[i]; best = i; }
                }
                used[best] = true;
                srank1[best] = r;
                g_sel[b][1 + r] = L1B + best;
                int gy = best >> 1, gx = best & 1;
                float* cp = dout + OFS_COORDS + ((size_t)b * ROWS + 1 + r) * 4;
                cp[0] = (gx + 0.5f) * 0.5f; cp[1] = (gy + 0.5f) * 0.5f;
                cp[2] = 0.5f; cp[3] = 0.5f;
            }
        }
        __syncwarp();

        // level 2: g=4, k=8 (warp-parallel argmax)
        {
            float v = NEG_INF;
            if (lane < 16) {
                int gy = lane >> 2, gx = lane & 3;
                v = fabsf(sl2[L2B + lane] - sl2[(2 * gy) * 8 + 2 * gx]);
            }
            for (int r = 0; r < 8; r++) {
                float bv = v; int bi = lane;
                warp_argmax(bv, bi);
                if (lane == bi) v = NEG_INF;
                if (lane == 0) {
                    srank2[bi] = r;
                    g_sel[b][5 + r] = L2B + bi;
                    int gy = bi >> 2, gx = bi & 3;
                    float* cp = dout + OFS_COORDS + ((size_t)b * ROWS + 5 + r) * 4;
                    cp[0] = (gx + 0.5f) * 0.25f; cp[1] = (gy + 0.5f) * 0.25f;
                    cp[2] = 0.25f; cp[3] = 0.25f;
                }
            }
        }
        // level 3: g=8, k=19 (2 candidates per lane)
        {
            float a0 = sl2[lane], a1 = sl2[lane + 32];
            for (int r = 0; r < 19; r++) {
                float bv; int bi;
                if (a0 >= a1) { bv = a0; bi = lane; }
                else          { bv = a1; bi = lane + 32; }
                warp_argmax(bv, bi);
                if (bi == lane)      a0 = NEG_INF;
                if (bi == lane + 32) a1 = NEG_INF;
                if (lane == 0) {
                    srank3[bi] = r;
                    g_sel[b][13 + r] = bi;
                    int gy = bi >> 3, gx = bi & 7;
                    float* cp = dout + OFS_COORDS + ((size_t)b * ROWS + 13 + r) * 4;
                    cp[0] = (gx + 0.5f) * 0.125f; cp[1] = (gy + 0.5f) * 0.125f;
                    cp[2] = 0.125f; cp[3] = 0.125f;
                }
            }
        }
        __syncwarp();

        // fine-cell -> row map (finest kept level wins; level 1 covers all)
        #pragma unroll
        for (int h = 0; h < 2; h++) {
            int cell = lane + 32 * h;
            int gy = cell >> 3, gx = cell & 7;
            int row;
            if (srank3[cell] >= 0) {
                row = 13 + srank3[cell];
            } else {
                int c2 = (gy >> 1) * 4 + (gx >> 1);
                if (srank2[c2] >= 0) row = 5 + srank2[c2];
                else                 row = 1 + srank1[(gy >> 2) * 2 + (gx >> 2)];
            }
            g_map8[b][cell] = row;
        }
        if (b == 0 && lane == 0) dout[OFS_SPARSITY] = 32.0f / 65536.0f;
    }
}

// ---------------------------------------------------------------------------
// K3: LayerNorm + Linear(256->256), 8 rows per block (w read amortized 8x).
// ---------------------------------------------------------------------------
__global__ void k_proj(const float* __restrict__ ln_g, const float* __restrict__ ln_b,
                       const float* __restrict__ wmat, const float* __restrict__ bias,
                       float* __restrict__ dout) {
    int blk = blockIdx.x;         // 16 blocks: (b, rowgroup)
    int b   = blk >> 2;
    int r0  = (blk & 3) * 8;
    int t   = threadIdx.x;        // 256 threads
    int lane = t & 31, w = t >> 5;

    __shared__ float sred[8];
    __shared__ float skf[8][C_];

    float lg = ln_g[t], lb = ln_b[t];

    #pragma unroll
    for (int r = 0; r < 8; r++) {
        int cell = g_sel[b][r0 + r];
        float v = g_pyr[b][cell][t];
        // mean
        float s = v;
        #pragma unroll
        for (int o = 16; o > 0; o >>= 1) s += __shfl_xor_sync(0xffffffffu, s, o);
        if (lane == 0) sred[w] = s;
        __syncthreads();
        float mean = 0.f;
        #pragma unroll
        for (int i = 0; i < 8; i++) mean += sred[i];
        mean *= (1.0f / 256.0f);
        __syncthreads();
        // variance
        float d = v - mean;
        float s2 = d * d;
        #pragma unroll
        for (int o = 16; o > 0; o >>= 1) s2 += __shfl_xor_sync(0xffffffffu, s2, o);
        if (lane == 0) sred[w] = s2;
        __syncthreads();
        float var = 0.f;
        #pragma unroll
        for (int i = 0; i < 8; i++) var += sred[i];
        var *= (1.0f / 256.0f);
        skf[r][t] = d * rsqrtf(var + 1e-5f) * lg + lb;
        __syncthreads();
    }

    float acc[8];
    float bs = bias[t];
    #pragma unroll
    for (int r = 0; r < 8; r++) acc[r] = bs;

    #pragma unroll 4
    for (int c = 0; c < 256; c++) {
        float wv = wmat[c * 256 + t];
        #pragma unroll
        for (int r = 0; r < 8; r++)
            acc[r] = fmaf(skf[r][c], wv, acc[r]);
    }
    #pragma unroll
    for (int r = 0; r < 8; r++)
        dout[OFS_SPARSE + ((size_t)(b * 32 + r0 + r)) * 256 + t] = acc[r];
}

// ---------------------------------------------------------------------------
// K4: dense fill. One block per (b, d, 32-row strip). Pure float4 stores.
// ---------------------------------------------------------------------------
__global__ void k_fill(float* __restrict__ dout) {
    int y8 = blockIdx.x & 7;
    int d  = (blockIdx.x >> 3) & 255;
    int b  = blockIdx.x >> 11;
    int t  = threadIdx.x;   // 256 threads

    __shared__ float sv[8];
    if (t < 8) {
        int row = g_map8[b][y8 * 8 + t];
        sv[t] = dout[OFS_SPARSE + ((size_t)(b * 32 + row)) * 256 + d];
    }
    __syncthreads();

    float4* base = reinterpret_cast<float4*>(
        dout + ((size_t)((b * 256 + d) * 256 + y8 * 32)) * 256);
    #pragma unroll
    for (int i = 0; i < 8; i++) {
        int f  = t + i * 256;       // float4 index within the 32x256 slab
        float v = sv[(f & 63) >> 3];
        base[f] = make_float4(v, v, v, v);
    }
}

// ---------------------------------------------------------------------------
extern "C" void kernel_launch(void* const* d_in, const int* in_sizes, int n_in,
                              void* d_out, int out_size) {
    const float* x    = (const float*)d_in[0];
    const float* ln_g = (const float*)d_in[1];
    const float* ln_b = (const float*)d_in[2];
    const float* w    = (const float*)d_in[3];
    const float* bias = (const float*)d_in[4];
    float* out = (float*)d_out;
    (void)in_sizes; (void)n_in; (void)out_size;

    k_pool<<<B_ * C_ * 8, 256>>>(x);
    k_prep<<<B_, 256>>>(out);
    k_proj<<<B_ * 4, 256>>>(ln_g, ln_b, w, bias, out);
    k_fill<<<B_ * CO_ * 8, 256>>>(out);
}

// round 3
// speedup vs baseline: 1.2957x; 1.1798x over previous
#include <cuda_runtime.h>
#include <math.h>

#define B_   4
#define C_   256
#define CO_  256
#define NTOT 85          // 64 (g=8) + 16 (g=4) + 4 (g=2) + 1 (g=1)
#define L3B  0
#define L2B  64
#define L1B  80
#define L0B  84
#define ROWS 32          // 1 + 4 + 8 + 19 kept rows per batch

// Output offsets (floats): (out, sparse_seq, all_coords, sparsity)
#define OFS_SPARSE   67108864ull                    // 4*256*256*256
#define OFS_COORDS   (67108864ull + 32768ull)       // + 4*32*256
#define OFS_SPARSITY (67108864ull + 32768ull + 512ull)

#define NEG_INF __int_as_float(0xff800000)

// Scratch (device globals — allocations forbidden). Cell-major for coalescing.
__device__ float g_pyr[B_][NTOT][C_];   // pyramid, cell-major
__device__ int   g_sel[B_][ROWS];       // kept cell index [0,85) per row
__device__ int   g_map8[B_][64];        // finest-kept row per 8x8 fine cell

// ---------------------------------------------------------------------------
// K1: grid max pool x -> pyr3 (g=8). One WARP per 32x32 cell.
// 8 streaming float4 loads per lane, one 5-step shuffle reduction.
// Block = 256 threads = 8 warps = the 8 gx cells of one (b,c,gy) strip.
// ---------------------------------------------------------------------------
__global__ void k_pool(const float* __restrict__ x) {
    int gy = blockIdx.x & 7;
    int bc = blockIdx.x >> 3;
    int c  = bc & 255;
    int b  = bc >> 8;

    int t    = threadIdx.x;
    int lane = t & 31;
    int gx   = t >> 5;            // warp id = gx

    const float4* base4 = reinterpret_cast<const float4*>(
        x + ((size_t)(b * 256 + c) * 256 + (size_t)gy * 32) * 256) + gx * 8;

    int r0 = lane >> 3;           // row offset within group of 4
    int f4 = lane & 7;            // float4 within the 32-float cell row

    float m = NEG_INF;
    #pragma unroll
    for (int i = 0; i < 8; i++) {
        float4 v = __ldcs(base4 + (size_t)(i * 4 + r0) * 64 + f4);
        m = fmaxf(m, fmaxf(fmaxf(v.x, v.y), fmaxf(v.z, v.w)));
    }
    #pragma unroll
    for (int o = 16; o > 0; o >>= 1)
        m = fmaxf(m, __shfl_xor_sync(0xffffffffu, m, o));
    if (lane == 0) g_pyr[b][gy * 8 + gx][c] = m;
}

// ---------------------------------------------------------------------------
// K2: per-batch prep: pyramid upper levels + L2 norms + top-k + coords + map.
// ---------------------------------------------------------------------------
__device__ __forceinline__ void warp_argmax(float& v, int& i) {
    #pragma unroll
    for (int o = 16; o > 0; o >>= 1) {
        float ov = __shfl_xor_sync(0xffffffffu, v, o);
        int   oi = __shfl_xor_sync(0xffffffffu, i, o);
        if (ov > v || (ov == v && oi < i)) { v = ov; i = oi; }
    }
}

__global__ void k_prep(float* __restrict__ dout) {
    int b = blockIdx.x;
    int t = threadIdx.x;          // 256 threads (= channel in phase A)
    int lane = t & 31, w = t >> 5;

    // --- phase A: upper pyramid levels (per-channel, fully coalesced) ---
    float v2a[16];
    #pragma unroll
    for (int u = 0; u < 16; u++) {
        int gy = u >> 2, gx = u & 3;
        int c0 = (gy * 2) * 8 + gx * 2;
        float v = fmaxf(fmaxf(g_pyr[b][c0][t],     g_pyr[b][c0 + 1][t]),
                        fmaxf(g_pyr[b][c0 + 8][t], g_pyr[b][c0 + 9][t]));
        v2a[u] = v;
        g_pyr[b][L2B + u][t] = v;
    }
    float v1a[4];
    #pragma unroll
    for (int u = 0; u < 4; u++) {
        int gy = u >> 1, gx = u & 1;
        int c0 = (gy * 2) * 4 + gx * 2;
        float v = fmaxf(fmaxf(v2a[c0], v2a[c0 + 1]), fmaxf(v2a[c0 + 4], v2a[c0 + 5]));
        v1a[u] = v;
        g_pyr[b][L1B + u][t] = v;
    }
    g_pyr[b][L0B][t] = fmaxf(fmaxf(v1a[0], v1a[1]), fmaxf(v1a[2], v1a[3]));
    __syncthreads();

    // --- phase B: L2 norms per cell (8 warps stripe the 85 cells) ---
    __shared__ float sl2[NTOT];
    for (int u = w; u < NTOT; u += 8) {
        float acc = 0.f;
        #pragma unroll
        for (int i = 0; i < 8; i++) {
            float v = g_pyr[b][u][lane + 32 * i];
            acc = fmaf(v, v, acc);
        }
        #pragma unroll
        for (int o = 16; o > 0; o >>= 1)
            acc += __shfl_xor_sync(0xffffffffu, acc, o);
        if (lane == 0) sl2[u] = sqrtf(acc);
    }
    __syncthreads();

    // --- phase C: top-k per level (warp 0 only) ---
    __shared__ int srank3[64], srank2[16], srank1[4];
    if (w == 0) {
        srank3[lane] = -1; srank3[lane + 32] = -1;
        if (lane < 16) srank2[lane] = -1;
        if (lane < 4)  srank1[lane] = -1;

        // level 0: g=1, k=1, row 0
        if (lane == 0) {
            g_sel[b][0] = L0B;
            float* cp = dout + OFS_COORDS + ((size_t)b * ROWS) * 4;
            cp[0] = 0.5f; cp[1] = 0.5f; cp[2] = 1.0f; cp[3] = 1.0f;
        }
        // level 1: g=2, k=4 (serial on lane 0, N=4)
        if (lane == 0) {
            float imp[4];
            #pragma unroll
            for (int n = 0; n < 4; n++) {
                int gy = n >> 1, gx = n & 1;
                imp[n] = fabsf(sl2[L1B + n] - sl2[L2B + (2 * gy) * 4 + 2 * gx]);
            }
            bool used[4] = {false, false, false, false};
            for (int r = 0; r < 4; r++) {
                int best = -1; float bv = 0.f;
                #pragma unroll
                for (int i = 0; i < 4; i++) {
                    if (used[i]) continue;
                    if (best < 0 || imp[i] > bv) { bv = imp[i]; best = i; }
                }
                used[best] = true;
                srank1[best] = r;
                g_sel[b][1 + r] = L1B + best;
                int gy = best >> 1, gx = best & 1;
                float* cp = dout + OFS_COORDS + ((size_t)b * ROWS + 1 + r) * 4;
                cp[0] = (gx + 0.5f) * 0.5f; cp[1] = (gy + 0.5f) * 0.5f;
                cp[2] = 0.5f; cp[3] = 0.5f;
            }
        }
        __syncwarp();

        // level 2: g=4, k=8 (warp-parallel argmax)
        {
            float v = NEG_INF;
            if (lane < 16) {
                int gy = lane >> 2, gx = lane & 3;
                v = fabsf(sl2[L2B + lane] - sl2[(2 * gy) * 8 + 2 * gx]);
            }
            for (int r = 0; r < 8; r++) {
                float bv = v; int bi = lane;
                warp_argmax(bv, bi);
                if (lane == bi) v = NEG_INF;
                if (lane == 0) {
                    srank2[bi] = r;
                    g_sel[b][5 + r] = L2B + bi;
                    int gy = bi >> 2, gx = bi & 3;
                    float* cp = dout + OFS_COORDS + ((size_t)b * ROWS + 5 + r) * 4;
                    cp[0] = (gx + 0.5f) * 0.25f; cp[1] = (gy + 0.5f) * 0.25f;
                    cp[2] = 0.25f; cp[3] = 0.25f;
                }
            }
        }
        // level 3: g=8, k=19 (2 candidates per lane)
        {
            float a0 = sl2[lane], a1 = sl2[lane + 32];
            for (int r = 0; r < 19; r++) {
                float bv; int bi;
                if (a0 >= a1) { bv = a0; bi = lane; }
                else          { bv = a1; bi = lane + 32; }
                warp_argmax(bv, bi);
                if (bi == lane)      a0 = NEG_INF;
                if (bi == lane + 32) a1 = NEG_INF;
                if (lane == 0) {
                    srank3[bi] = r;
                    g_sel[b][13 + r] = bi;
                    int gy = bi >> 3, gx = bi & 7;
                    float* cp = dout + OFS_COORDS + ((size_t)b * ROWS + 13 + r) * 4;
                    cp[0] = (gx + 0.5f) * 0.125f; cp[1] = (gy + 0.5f) * 0.125f;
                    cp[2] = 0.125f; cp[3] = 0.125f;
                }
            }
        }
        __syncwarp();

        // fine-cell -> row map (finest kept level wins; level 1 covers all)
        #pragma unroll
        for (int h = 0; h < 2; h++) {
            int cell = lane + 32 * h;
            int gy = cell >> 3, gx = cell & 7;
            int row;
            if (srank3[cell] >= 0) {
                row = 13 + srank3[cell];
            } else {
                int c2 = (gy >> 1) * 4 + (gx >> 1);
                if (srank2[c2] >= 0) row = 5 + srank2[c2];
                else                 row = 1 + srank1[(gy >> 2) * 2 + (gx >> 2)];
            }
            g_map8[b][cell] = row;
        }
        if (b == 0 && lane == 0) dout[OFS_SPARSITY] = 32.0f / 65536.0f;
    }
}

// ---------------------------------------------------------------------------
// K3: LayerNorm + Linear(256->256), 4 rows per block (32 blocks).
// ---------------------------------------------------------------------------
__global__ void k_proj(const float* __restrict__ ln_g, const float* __restrict__ ln_b,
                       const float* __restrict__ wmat, const float* __restrict__ bias,
                       float* __restrict__ dout) {
    int blk = blockIdx.x;         // 32 blocks: (b, rowgroup)
    int b   = blk >> 3;
    int r0  = (blk & 7) * 4;
    int t   = threadIdx.x;        // 256 threads
    int lane = t & 31, w = t >> 5;

    __shared__ float sred[8];
    __shared__ float skf[4][C_];

    float lg = ln_g[t], lb = ln_b[t];

    #pragma unroll
    for (int r = 0; r < 4; r++) {
        int cell = g_sel[b][r0 + r];
        float v = g_pyr[b][cell][t];
        // mean
        float s = v;
        #pragma unroll
        for (int o = 16; o > 0; o >>= 1) s += __shfl_xor_sync(0xffffffffu, s, o);
        if (lane == 0) sred[w] = s;
        __syncthreads();
        float mean = 0.f;
        #pragma unroll
        for (int i = 0; i < 8; i++) mean += sred[i];
        mean *= (1.0f / 256.0f);
        __syncthreads();
        // variance
        float d = v - mean;
        float s2 = d * d;
        #pragma unroll
        for (int o = 16; o > 0; o >>= 1) s2 += __shfl_xor_sync(0xffffffffu, s2, o);
        if (lane == 0) sred[w] = s2;
        __syncthreads();
        float var = 0.f;
        #pragma unroll
        for (int i = 0; i < 8; i++) var += sred[i];
        var *= (1.0f / 256.0f);
        skf[r][t] = d * rsqrtf(var + 1e-5f) * lg + lb;
        __syncthreads();
    }

    float acc[4];
    float bs = bias[t];
    #pragma unroll
    for (int r = 0; r < 4; r++) acc[r] = bs;

    #pragma unroll 4
    for (int c = 0; c < 256; c++) {
        float wv = wmat[c * 256 + t];
        #pragma unroll
        for (int r = 0; r < 4; r++)
            acc[r] = fmaf(skf[r][c], wv, acc[r]);
    }
    #pragma unroll
    for (int r = 0; r < 4; r++)
        dout[OFS_SPARSE + ((size_t)(b * 32 + r0 + r)) * 256 + t] = acc[r];
}

// ---------------------------------------------------------------------------
// K4: dense fill. One block per (b, d, 32-row strip). Streaming float4 stores.
// ---------------------------------------------------------------------------
__global__ void k_fill(float* __restrict__ dout) {
    int y8 = blockIdx.x & 7;
    int d  = (blockIdx.x >> 3) & 255;
    int b  = blockIdx.x >> 11;
    int t  = threadIdx.x;   // 256 threads

    __shared__ float sv[8];
    if (t < 8) {
        int row = g_map8[b][y8 * 8 + t];
        sv[t] = dout[OFS_SPARSE + ((size_t)(b * 32 + row)) * 256 + d];
    }
    __syncthreads();

    float4* base = reinterpret_cast<float4*>(
        dout + ((size_t)((b * 256 + d) * 256 + y8 * 32)) * 256);
    #pragma unroll
    for (int i = 0; i < 8; i++) {
        int f  = t + i * 256;       // float4 index within the 32x256 slab
        float v = sv[(f & 63) >> 3];
        __stcs(base + f, make_float4(v, v, v, v));
    }
}

// ---------------------------------------------------------------------------
extern "C" void kernel_launch(void* const* d_in, const int* in_sizes, int n_in,
                              void* d_out, int out_size) {
    const float* x    = (const float*)d_in[0];
    const float* ln_g = (const float*)d_in[1];
    const float* ln_b = (const float*)d_in[2];
    const float* w    = (const float*)d_in[3];
    const float* bias = (const float*)d_in[4];
    float* out = (float*)d_out;
    (void)in_sizes; (void)n_in; (void)out_size;

    k_pool<<<B_ * C_ * 8, 256>>>(x);
    k_prep<<<B_, 256>>>(out);
    k_proj<<<B_ * 8, 256>>>(ln_g, ln_b, w, bias, out);
    k_fill<<<B_ * CO_ * 8, 256>>>(out);
}

// round 4
// speedup vs baseline: 1.3938x; 1.0757x over previous
#include <cuda_runtime.h>
#include <math.h>

#define B_   4
#define C_   256
#define CO_  256
#define NTOT 85          // 64 (g=8) + 16 (g=4) + 4 (g=2) + 1 (g=1)
#define L3B  0
#define L2B  64
#define L1B  80
#define L0B  84
#define ROWS 32          // 1 + 4 + 8 + 19 kept rows per batch

// Output offsets (floats): (out, sparse_seq, all_coords, sparsity)
#define OFS_SPARSE   67108864ull                    // 4*256*256*256
#define OFS_COORDS   (67108864ull + 32768ull)       // + 4*32*256
#define OFS_SPARSITY (67108864ull + 32768ull + 512ull)

#define NEG_INF __int_as_float(0xff800000)

// Scratch (device globals — allocations forbidden). Cell-major for coalescing.
__device__ float    g_pyr[B_][NTOT][C_];   // pyramid, cell-major
__device__ int      g_sel[B_][ROWS];       // kept cell index [0,85) per row
__device__ int      g_map8[B_][64];        // finest-kept row per 8x8 fine cell
__device__ unsigned g_flag_prep[B_];       // prep(b) done
__device__ unsigned g_flag_proj[B_];       // #proj blocks done for b (8 = done)

// ---------------------------------------------------------------------------
// K1: grid max pool x -> pyr3 (g=8). One WARP per 32x32 cell.
// Also resets the post-kernel flags (pool fully precedes k_post).
// ---------------------------------------------------------------------------
__global__ void k_pool(const float* __restrict__ x) {
    if (blockIdx.x == 0 && threadIdx.x < 2 * B_) {
        if (threadIdx.x < B_) g_flag_prep[threadIdx.x] = 0u;
        else                  g_flag_proj[threadIdx.x - B_] = 0u;
    }
    int gy = blockIdx.x & 7;
    int bc = blockIdx.x >> 3;
    int c  = bc & 255;
    int b  = bc >> 8;

    int t    = threadIdx.x;
    int lane = t & 31;
    int gx   = t >> 5;            // warp id = gx

    const float4* base4 = reinterpret_cast<const float4*>(
        x + ((size_t)(b * 256 + c) * 256 + (size_t)gy * 32) * 256) + gx * 8;

    int r0 = lane >> 3;           // row offset within group of 4
    int f4 = lane & 7;            // float4 within the 32-float cell row

    float m = NEG_INF;
    #pragma unroll
    for (int i = 0; i < 8; i++) {
        float4 v = __ldcs(base4 + (size_t)(i * 4 + r0) * 64 + f4);
        m = fmaxf(m, fmaxf(fmaxf(v.x, v.y), fmaxf(v.z, v.w)));
    }
    #pragma unroll
    for (int o = 16; o > 0; o >>= 1)
        m = fmaxf(m, __shfl_xor_sync(0xffffffffu, m, o));
    if (lane == 0) g_pyr[b][gy * 8 + gx][c] = m;
}

// ---------------------------------------------------------------------------
__device__ __forceinline__ void warp_argmax(float& v, int& i) {
    #pragma unroll
    for (int o = 16; o > 0; o >>= 1) {
        float ov = __shfl_xor_sync(0xffffffffu, v, o);
        int   oi = __shfl_xor_sync(0xffffffffu, i, o);
        if (ov > v || (ov == v && oi < i)) { v = ov; i = oi; }
    }
}

// prep: pyramid upper levels + L2 norms + top-k + coords + map for batch b.
__device__ void do_prep(int b, float* __restrict__ dout) {
    int t = threadIdx.x;
    int lane = t & 31, w = t >> 5;

    // --- phase A: upper pyramid levels ---
    float v2a[16];
    #pragma unroll
    for (int u = 0; u < 16; u++) {
        int gy = u >> 2, gx = u & 3;
        int c0 = (gy * 2) * 8 + gx * 2;
        float v = fmaxf(fmaxf(g_pyr[b][c0][t],     g_pyr[b][c0 + 1][t]),
                        fmaxf(g_pyr[b][c0 + 8][t], g_pyr[b][c0 + 9][t]));
        v2a[u] = v;
        g_pyr[b][L2B + u][t] = v;
    }
    float v1a[4];
    #pragma unroll
    for (int u = 0; u < 4; u++) {
        int gy = u >> 1, gx = u & 1;
        int c0 = (gy * 2) * 4 + gx * 2;
        float v = fmaxf(fmaxf(v2a[c0], v2a[c0 + 1]), fmaxf(v2a[c0 + 4], v2a[c0 + 5]));
        v1a[u] = v;
        g_pyr[b][L1B + u][t] = v;
    }
    g_pyr[b][L0B][t] = fmaxf(fmaxf(v1a[0], v1a[1]), fmaxf(v1a[2], v1a[3]));
    __syncthreads();

    // --- phase B: L2 norms per cell ---
    __shared__ float sl2[NTOT];
    for (int u = w; u < NTOT; u += 8) {
        float acc = 0.f;
        #pragma unroll
        for (int i = 0; i < 8; i++) {
            float v = g_pyr[b][u][lane + 32 * i];
            acc = fmaf(v, v, acc);
        }
        #pragma unroll
        for (int o = 16; o > 0; o >>= 1)
            acc += __shfl_xor_sync(0xffffffffu, acc, o);
        if (lane == 0) sl2[u] = sqrtf(acc);
    }
    __syncthreads();

    // --- phase C: top-k per level (warp 0 only) ---
    __shared__ int srank3[64], srank2[16], srank1[4];
    if (w == 0) {
        srank3[lane] = -1; srank3[lane + 32] = -1;
        if (lane < 16) srank2[lane] = -1;
        if (lane < 4)  srank1[lane] = -1;

        if (lane == 0) {
            g_sel[b][0] = L0B;
            float* cp = dout + OFS_COORDS + ((size_t)b * ROWS) * 4;
            cp[0] = 0.5f; cp[1] = 0.5f; cp[2] = 1.0f; cp[3] = 1.0f;
        }
        // level 1: g=2, k=4 (serial on lane 0, N=4)
        if (lane == 0) {
            float imp[4];
            #pragma unroll
            for (int n = 0; n < 4; n++) {
                int gy = n >> 1, gx = n & 1;
                imp[n] = fabsf(sl2[L1B + n] - sl2[L2B + (2 * gy) * 4 + 2 * gx]);
            }
            bool used[4] = {false, false, false, false};
            for (int r = 0; r < 4; r++) {
                int best = -1; float bv = 0.f;
                #pragma unroll
                for (int i = 0; i < 4; i++) {
                    if (used[i]) continue;
                    if (best < 0 || imp[i] > bv) { bv = imp[i]; best = i; }
                }
                used[best] = true;
                srank1[best] = r;
                g_sel[b][1 + r] = L1B + best;
                int gy = best >> 1, gx = best & 1;
                float* cp = dout + OFS_COORDS + ((size_t)b * ROWS + 1 + r) * 4;
                cp[0] = (gx + 0.5f) * 0.5f; cp[1] = (gy + 0.5f) * 0.5f;
                cp[2] = 0.5f; cp[3] = 0.5f;
            }
        }
        __syncwarp();

        // level 2: g=4, k=8
        {
            float v = NEG_INF;
            if (lane < 16) {
                int gy = lane >> 2, gx = lane & 3;
                v = fabsf(sl2[L2B + lane] - sl2[(2 * gy) * 8 + 2 * gx]);
            }
            for (int r = 0; r < 8; r++) {
                float bv = v; int bi = lane;
                warp_argmax(bv, bi);
                if (lane == bi) v = NEG_INF;
                if (lane == 0) {
                    srank2[bi] = r;
                    g_sel[b][5 + r] = L2B + bi;
                    int gy = bi >> 2, gx = bi & 3;
                    float* cp = dout + OFS_COORDS + ((size_t)b * ROWS + 5 + r) * 4;
                    cp[0] = (gx + 0.5f) * 0.25f; cp[1] = (gy + 0.5f) * 0.25f;
                    cp[2] = 0.25f; cp[3] = 0.25f;
                }
            }
        }
        // level 3: g=8, k=19
        {
            float a0 = sl2[lane], a1 = sl2[lane + 32];
            for (int r = 0; r < 19; r++) {
                float bv; int bi;
                if (a0 >= a1) { bv = a0; bi = lane; }
                else          { bv = a1; bi = lane + 32; }
                warp_argmax(bv, bi);
                if (bi == lane)      a0 = NEG_INF;
                if (bi == lane + 32) a1 = NEG_INF;
                if (lane == 0) {
                    srank3[bi] = r;
                    g_sel[b][13 + r] = bi;
                    int gy = bi >> 3, gx = bi & 7;
                    float* cp = dout + OFS_COORDS + ((size_t)b * ROWS + 13 + r) * 4;
                    cp[0] = (gx + 0.5f) * 0.125f; cp[1] = (gy + 0.5f) * 0.125f;
                    cp[2] = 0.125f; cp[3] = 0.125f;
                }
            }
        }
        __syncwarp();

        // fine-cell -> row map
        #pragma unroll
        for (int h = 0; h < 2; h++) {
            int cell = lane + 32 * h;
            int gy = cell >> 3, gx = cell & 7;
            int row;
            if (srank3[cell] >= 0) {
                row = 13 + srank3[cell];
            } else {
                int c2 = (gy >> 1) * 4 + (gx >> 1);
                if (srank2[c2] >= 0) row = 5 + srank2[c2];
                else                 row = 1 + srank1[(gy >> 2) * 2 + (gx >> 2)];
            }
            g_map8[b][cell] = row;
        }
        if (b == 0 && lane == 0) dout[OFS_SPARSITY] = 32.0f / 65536.0f;
    }
    __syncthreads();
}

// proj: LayerNorm + Linear for 4 rows of batch b (w loop MLP=16).
__device__ void do_proj(int b, int r0,
                        const float* __restrict__ ln_g, const float* __restrict__ ln_b,
                        const float* __restrict__ wmat, const float* __restrict__ bias,
                        float* __restrict__ dout) {
    int t = threadIdx.x;
    int lane = t & 31, w = t >> 5;

    __shared__ float sred[8];
    __shared__ float skf[4][C_];

    float lg = ln_g[t], lb = ln_b[t];

    #pragma unroll
    for (int r = 0; r < 4; r++) {
        int cell = __ldcg(&g_sel[b][r0 + r]);
        float v = __ldcg(&g_pyr[b][cell][t]);
        float s = v;
        #pragma unroll
        for (int o = 16; o > 0; o >>= 1) s += __shfl_xor_sync(0xffffffffu, s, o);
        if (lane == 0) sred[w] = s;
        __syncthreads();
        float mean = 0.f;
        #pragma unroll
        for (int i = 0; i < 8; i++) mean += sred[i];
        mean *= (1.0f / 256.0f);
        __syncthreads();
        float d = v - mean;
        float s2 = d * d;
        #pragma unroll
        for (int o = 16; o > 0; o >>= 1) s2 += __shfl_xor_sync(0xffffffffu, s2, o);
        if (lane == 0) sred[w] = s2;
        __syncthreads();
        float var = 0.f;
        #pragma unroll
        for (int i = 0; i < 8; i++) var += sred[i];
        var *= (1.0f / 256.0f);
        skf[r][t] = d * rsqrtf(var + 1e-5f) * lg + lb;
        __syncthreads();
    }

    float acc0 = bias[t], acc1 = acc0, acc2 = acc0, acc3 = acc0;

    #pragma unroll
    for (int c0 = 0; c0 < 256; c0 += 16) {
        float wv[16];
        #pragma unroll
        for (int j = 0; j < 16; j++) wv[j] = wmat[(c0 + j) * 256 + t];
        #pragma unroll
        for (int j = 0; j < 16; j++) {
            acc0 = fmaf(skf[0][c0 + j], wv[j], acc0);
            acc1 = fmaf(skf[1][c0 + j], wv[j], acc1);
            acc2 = fmaf(skf[2][c0 + j], wv[j], acc2);
            acc3 = fmaf(skf[3][c0 + j], wv[j], acc3);
        }
    }
    dout[OFS_SPARSE + ((size_t)(b * 32 + r0 + 0)) * 256 + t] = acc0;
    dout[OFS_SPARSE + ((size_t)(b * 32 + r0 + 1)) * 256 + t] = acc1;
    dout[OFS_SPARSE + ((size_t)(b * 32 + r0 + 2)) * 256 + t] = acc2;
    dout[OFS_SPARSE + ((size_t)(b * 32 + r0 + 3)) * 256 + t] = acc3;
}

// ---------------------------------------------------------------------------
// K2 (merged): prep (bid 0..3) -> proj (bid 4..35) -> fill (bid 36..8227),
// ordered via per-batch release/acquire flags. All producers land in wave 1.
// ---------------------------------------------------------------------------
__global__ void __launch_bounds__(256, 4)
k_post(const float* __restrict__ ln_g, const float* __restrict__ ln_b,
       const float* __restrict__ wmat, const float* __restrict__ bias,
       float* __restrict__ dout) {
    int bid = blockIdx.x;
    int t   = threadIdx.x;

    if (bid < 4) {
        do_prep(bid, dout);
        __threadfence();
        if (t == 0) atomicExch(&g_flag_prep[bid], 1u);
        return;
    }
    if (bid < 36) {
        int idx = bid - 4;
        int b   = idx >> 3;
        int r0  = (idx & 7) * 4;
        if (t == 0) {
            while (atomicAdd(&g_flag_prep[b], 0u) == 0u) __nanosleep(128);
        }
        __syncthreads();
        do_proj(b, r0, ln_g, ln_b, wmat, bias, dout);
        __threadfence();
        if (t == 0) atomicAdd(&g_flag_proj[b], 1u);
        return;
    }
    // fill
    int f  = bid - 36;
    int y8 = f & 7;
    int d  = (f >> 3) & 255;
    int b  = f >> 11;

    if (t == 0) {
        while (atomicAdd(&g_flag_proj[b], 0u) < 8u) __nanosleep(128);
    }
    __syncthreads();

    __shared__ float sv[8];
    if (t < 8) {
        int row = __ldcg(&g_map8[b][y8 * 8 + t]);
        sv[t] = __ldcg(dout + OFS_SPARSE + ((size_t)(b * 32 + row)) * 256 + d);
    }
    __syncthreads();

    float4* base = reinterpret_cast<float4*>(
        dout + ((size_t)((b * 256 + d) * 256 + y8 * 32)) * 256);
    #pragma unroll
    for (int i = 0; i < 8; i++) {
        int ff = t + i * 256;
        float v = sv[(ff & 63) >> 3];
        __stcs(base + ff, make_float4(v, v, v, v));
    }
}

// ---------------------------------------------------------------------------
extern "C" void kernel_launch(void* const* d_in, const int* in_sizes, int n_in,
                              void* d_out, int out_size) {
    const float* x    = (const float*)d_in[0];
    const float* ln_g = (const float*)d_in[1];
    const float* ln_b = (const float*)d_in[2];
    const float* w    = (const float*)d_in[3];
    const float* bias = (const float*)d_in[4];
    float* out = (float*)d_out;
    (void)in_sizes; (void)n_in; (void)out_size;

    k_pool<<<B_ * C_ * 8, 256>>>(x);
    k_post<<<36 + B_ * CO_ * 8, 256>>>(ln_g, ln_b, w, bias, out);
}